// round 15
// baseline (speedup 1.0000x reference)
#include <cuda_runtime.h>
#include <cuda_bf16.h>
#include <cuda_fp16.h>
#include <stdint.h>
#include <math.h>

#define NN 50000
#define EE 600000
#define DD 128
#define D2 256
#define LL 7
#define BB 512
#define TT 10
#define BN_EPS 1e-5f
#define MSG_EPS 1e-7f
#define MT 391    // ceil(50000/128)
#define NSB 49    // ceil(50000/1024) scan blocks
#define NCOMBO 60 // 5*6*2 bond-attr combos

// ---------------- scratch ----------------
__device__ float g_h[NN * DD];
__device__ __nv_bfloat16 g_xh[NN * DD], g_xl[NN * DD]; // conv out, bf16 split
__device__ float g_z[NN * D2];
__device__ __half g_bt16[NCOMBO * DD];                 // bond combo table (fp16), L1-resident
__device__ uint8_t g_ecid[EE];                         // per sorted edge: combo id
__device__ int   g_deg[NN], g_rowptr[NN + 1], g_cursor[NN], g_srcs[EE];
__device__ int   g_bsum[64], g_boff[64];
__device__ float g_sum[D2], g_sumsq[D2];     // z stats
__device__ float g_hsum[DD], g_hsumsq[DD];   // h stats
__device__ float g_hsc[DD], g_hsh[DD];       // folded BN(h) for final pool
__device__ __nv_bfloat16 g_w1h[LL * D2 * DD], g_w1l[LL * D2 * DD];  // [l][n=256][k=128]
__device__ __nv_bfloat16 g_w2h[LL * DD * D2], g_w2l[LL * DD * D2];  // [l][n=128][k=256]
__device__ float g_pool[BB * DD];
__device__ float g_cnt[BB];

// ---------------- helpers ----------------
__device__ __forceinline__ uint32_t smem_u32(const void* p) {
    uint32_t a;
    asm("{ .reg .u64 t; cvta.to.shared.u64 t, %1; cvt.u32.u64 %0, t; }" : "=r"(a) : "l"(p));
    return a;
}
#define LDSM4(R, addr)                                                                      \
    asm volatile("ldmatrix.sync.aligned.m8n8.x4.shared.b16 {%0,%1,%2,%3}, [%4];"            \
        : "=r"((R)[0]), "=r"((R)[1]), "=r"((R)[2]), "=r"((R)[3]) : "r"(addr))

__device__ __forceinline__ void mma16816(float* c, const uint32_t* a, uint32_t b0, uint32_t b1) {
    asm volatile("mma.sync.aligned.m16n8k16.row.col.f32.bf16.bf16.f32 "
        "{%0,%1,%2,%3},{%4,%5,%6,%7},{%8,%9},{%0,%1,%2,%3};"
        : "+f"(c[0]), "+f"(c[1]), "+f"(c[2]), "+f"(c[3])
        : "r"(a[0]), "r"(a[1]), "r"(a[2]), "r"(a[3]), "r"(b0), "r"(b1));
}

__device__ __forceinline__ void split4(float4 v, uint2& H, uint2& Lo) {
    __nv_bfloat16 a = __float2bfloat16(v.x), b = __float2bfloat16(v.y);
    __nv_bfloat16 c = __float2bfloat16(v.z), d = __float2bfloat16(v.w);
    __nv_bfloat162 h0 = __halves2bfloat162(a, b), h1 = __halves2bfloat162(c, d);
    H.x = *(uint32_t*)&h0; H.y = *(uint32_t*)&h1;
    __nv_bfloat162 l0 = __floats2bfloat162_rn(v.x - __bfloat162float(a), v.y - __bfloat162float(b));
    __nv_bfloat162 l1 = __floats2bfloat162_rn(v.z - __bfloat162float(c), v.w - __bfloat162float(d));
    Lo.x = *(uint32_t*)&l0; Lo.y = *(uint32_t*)&l1;
}

// ---------------- setup kernels ----------------
__global__ void k_zero_all() {   // grid covers BB*DD
    int i = blockIdx.x * blockDim.x + threadIdx.x;
    if (i < NN) g_deg[i] = 0;
    if (i < D2) { g_sum[i] = 0.f; g_sumsq[i] = 0.f; }
    if (i < DD) { g_hsum[i] = 0.f; g_hsumsq[i] = 0.f; }
    if (i < BB * DD) g_pool[i] = 0.f;
    if (i < BB) g_cnt[i] = 0.f;
}
__global__ void k_hist(const int* __restrict__ dst) {
    int e = blockIdx.x * blockDim.x + threadIdx.x;
    if (e < EE) atomicAdd(&g_deg[dst[e]], 1);
}
__global__ void k_scan1() {   // <<<NSB,1024>>>
    __shared__ int sh[1024];
    int tid = threadIdx.x;
    int gid = blockIdx.x * 1024 + tid;
    int v = (gid < NN) ? g_deg[gid] : 0;
    sh[tid] = v;
    __syncthreads();
#pragma unroll
    for (int off = 1; off < 1024; off <<= 1) {
        int x = (tid >= off) ? sh[tid - off] : 0;
        __syncthreads();
        sh[tid] += x;
        __syncthreads();
    }
    if (gid < NN) g_rowptr[gid] = sh[tid] - v;
    if (tid == 1023) g_bsum[blockIdx.x] = sh[1023];
}
__global__ void k_scan2() {   // <<<1,32>>>
    if (threadIdx.x == 0) {
        int c = 0;
        for (int i = 0; i < NSB; i++) { g_boff[i] = c; c += g_bsum[i]; }
        g_rowptr[NN] = c;
    }
}
__global__ void k_scan3() {
    int i = blockIdx.x * blockDim.x + threadIdx.x;
    if (i < NN) {
        int r = g_rowptr[i] + g_boff[i >> 10];
        g_rowptr[i] = r;
        g_cursor[i] = r;
    }
}
__global__ void k_scatter(const int* __restrict__ src, const int* __restrict__ dst,
                          const int* __restrict__ eattr) {
    int e = blockIdx.x * blockDim.x + threadIdx.x;
    if (e < EE) {
        int p = atomicAdd(&g_cursor[dst[e]], 1);
        g_srcs[p] = src[e];
        int a0 = __ldg(&eattr[e * 3 + 0]);
        int a1 = __ldg(&eattr[e * 3 + 1]);
        int a2 = __ldg(&eattr[e * 3 + 2]);
        g_ecid[p] = (uint8_t)(a0 * 12 + a1 * 2 + a2);
    }
}
__global__ void k_atom(const int* __restrict__ x, const int* __restrict__ aoff,
                       const float* __restrict__ atab) {
    int idx = blockIdx.x * blockDim.x + threadIdx.x;
    if (idx >= NN * DD) return;
    int i = idx >> 7, d = idx & 127;
    float acc = 0.f;
#pragma unroll
    for (int f = 0; f < 9; f++) {
        int row = __ldg(&x[i * 9 + f]) + __ldg(&aoff[f]);
        acc += __ldg(&atab[row * DD + d]);
    }
    g_h[idx] = acc;
}
__global__ void k_btab(const int* __restrict__ boff, const float* __restrict__ btab) {
    int idx = blockIdx.x * blockDim.x + threadIdx.x;
    if (idx >= NCOMBO * DD) return;
    int cid = idx >> 7, d = idx & 127;
    int a0 = cid / 12, a1 = (cid % 12) / 2, a2 = cid & 1;
    float acc = __ldg(&btab[(a0 + __ldg(&boff[0])) * DD + d]) +
                __ldg(&btab[(a1 + __ldg(&boff[1])) * DD + d]) +
                __ldg(&btab[(a2 + __ldg(&boff[2])) * DD + d]);
    g_bt16[idx] = __float2half_rn(acc);
}
__global__ void k_wprep1(const float* __restrict__ w1) {
    int idx = blockIdx.x * blockDim.x + threadIdx.x;
    if (idx >= LL * D2 * DD) return;
    int l = idx / (D2 * DD), rem = idx % (D2 * DD);
    int n = rem / DD, k = rem % DD;
    float v = __ldg(&w1[(size_t)l * DD * D2 + k * D2 + n]);
    __nv_bfloat16 hi = __float2bfloat16(v);
    g_w1h[idx] = hi;
    g_w1l[idx] = __float2bfloat16(v - __bfloat162float(hi));
}
__global__ void k_wprep2(const float* __restrict__ w2) {
    int idx = blockIdx.x * blockDim.x + threadIdx.x;
    if (idx >= LL * DD * D2) return;
    int l = idx / (DD * D2), rem = idx % (DD * D2);
    int n = rem / D2, k = rem % D2;
    float v = __ldg(&w2[(size_t)l * D2 * DD + k * DD + n]);
    __nv_bfloat16 hi = __float2bfloat16(v);
    g_w2h[idx] = hi;
    g_w2l[idx] = __float2bfloat16(v - __bfloat162float(hi));
}
// final-pool BN finalize (only used once, after the layer loop)
__global__ void k_bnfin_h(const float* __restrict__ gamma, const float* __restrict__ beta) { // <<<1,128>>>
    int c = threadIdx.x;
    float mu = g_hsum[c] / (float)NN;
    float var = g_hsumsq[c] / (float)NN - mu * mu;
    float sc = rsqrtf(var + BN_EPS) * __ldg(&gamma[c]);
    g_hsc[c] = sc;
    g_hsh[c] = __ldg(&beta[c]) - mu * sc;
}

// ---------------- aggregation: 2 nodes/block, 4 edge-groups x 32 lanes x float4 ----------------
// BN(h) folded inline from raw h-stats; block 0 zeros z-stats for the following gemm1.
__global__ void __launch_bounds__(256) k_aggr(const float* __restrict__ gamma,
                                              const float* __restrict__ beta,
                                              const float* __restrict__ tarr,
                                              int layer, int use_bn) {
    __shared__ float4 rse[2][4][32], rsn[2][4][32];
    int tid = threadIdx.x, lane = tid & 31, grp = (tid >> 5) & 3, half = tid >> 7;
    int u = blockIdx.x * 2 + half;
    if (blockIdx.x == 0) { g_sum[tid] = 0.f; g_sumsq[tid] = 0.f; }   // z-stats for next gemm1
    int d4 = lane << 2;
    float4 sc4 = make_float4(1.f, 1.f, 1.f, 1.f);
    float4 sh4 = make_float4(0.f, 0.f, 0.f, 0.f);
    if (use_bn) {
        float4 hs = *(const float4*)&g_hsum[d4];
        float4 hq = *(const float4*)&g_hsumsq[d4];
        float4 gm = __ldg((const float4*)&gamma[d4]);
        float4 bt = __ldg((const float4*)&beta[d4]);
        const float inv = 1.f / (float)NN;
        float mu0 = hs.x * inv, mu1 = hs.y * inv, mu2 = hs.z * inv, mu3 = hs.w * inv;
        sc4.x = rsqrtf(hq.x * inv - mu0 * mu0 + BN_EPS) * gm.x;
        sc4.y = rsqrtf(hq.y * inv - mu1 * mu1 + BN_EPS) * gm.y;
        sc4.z = rsqrtf(hq.z * inv - mu2 * mu2 + BN_EPS) * gm.z;
        sc4.w = rsqrtf(hq.w * inv - mu3 * mu3 + BN_EPS) * gm.w;
        sh4.x = bt.x - mu0 * sc4.x;
        sh4.y = bt.y - mu1 * sc4.y;
        sh4.z = bt.z - mu2 * sc4.z;
        sh4.w = bt.w - mu3 * sc4.w;
    }
    int beg = g_rowptr[u];
    int deg = g_rowptr[u + 1] - beg;
    float tl = __ldg(&tarr[layer]);
    float4 se = make_float4(0.f, 0.f, 0.f, 0.f);
    float4 sn = make_float4(0.f, 0.f, 0.f, 0.f);
    for (int j = grp; j < deg; j += 4) {
        int s = __ldg(&g_srcs[beg + j]);
        int cid = (int)__ldg(&g_ecid[beg + j]);
        float4 cv = __ldg((const float4*)(g_h + (size_t)s * DD + d4));
        if (use_bn) {
            cv.x = fmaxf(fmaf(cv.x, sc4.x, sh4.x), 0.f);
            cv.y = fmaxf(fmaf(cv.y, sc4.y, sh4.y), 0.f);
            cv.z = fmaxf(fmaf(cv.z, sc4.z, sh4.z), 0.f);
            cv.w = fmaxf(fmaf(cv.w, sc4.w, sh4.w), 0.f);
        }
        uint2 eu = *(const uint2*)(g_bt16 + cid * DD + d4);
        float2 e01 = __half22float2(*(__half2*)&eu.x);
        float2 e23 = __half22float2(*(__half2*)&eu.y);
        float m0 = fmaxf(cv.x + e01.x, 0.f) + MSG_EPS;
        float m1 = fmaxf(cv.y + e01.y, 0.f) + MSG_EPS;
        float m2 = fmaxf(cv.z + e23.x, 0.f) + MSG_EPS;
        float m3 = fmaxf(cv.w + e23.y, 0.f) + MSG_EPS;
        float e0 = __expf(m0 * tl), e1 = __expf(m1 * tl);
        float e2 = __expf(m2 * tl), e3 = __expf(m3 * tl);
        se.x += e0; se.y += e1; se.z += e2; se.w += e3;
        sn.x = fmaf(m0, e0, sn.x); sn.y = fmaf(m1, e1, sn.y);
        sn.z = fmaf(m2, e2, sn.z); sn.w = fmaf(m3, e3, sn.w);
    }
    rse[half][grp][lane] = se;
    rsn[half][grp][lane] = sn;
    __syncthreads();
    if (grp == 0) {
#pragma unroll
        for (int g = 1; g < 4; g++) {
            float4 a = rse[half][g][lane], b = rsn[half][g][lane];
            se.x += a.x; se.y += a.y; se.z += a.z; se.w += a.w;
            sn.x += b.x; sn.y += b.y; sn.z += b.z; sn.w += b.w;
        }
        float4 hv = *(const float4*)(g_h + (size_t)u * DD + d4);
        float4 v;
        v.x = use_bn ? fmaxf(fmaf(hv.x, sc4.x, sh4.x), 0.f) : hv.x;
        v.y = use_bn ? fmaxf(fmaf(hv.y, sc4.y, sh4.y), 0.f) : hv.y;
        v.z = use_bn ? fmaxf(fmaf(hv.z, sc4.z, sh4.z), 0.f) : hv.z;
        v.w = use_bn ? fmaxf(fmaf(hv.w, sc4.w, sh4.w), 0.f) : hv.w;
        if (deg > 0) {
            v.x += sn.x / (se.x + 1e-16f);
            v.y += sn.y / (se.y + 1e-16f);
            v.z += sn.z / (se.z + 1e-16f);
            v.w += sn.w / (se.w + 1e-16f);
        }
        uint2 H, Lo;
        split4(v, H, Lo);
        *(uint2*)(g_xh + (size_t)u * DD + d4) = H;
        *(uint2*)(g_xl + (size_t)u * DD + d4) = Lo;
    }
}

// ---------------- GEMM1: z = x @ W1^T (+bias); A bf16 split, K=128, NC=256 ----------------
// CTA(0,0) zeros h-stats for the following gemm2.
__global__ void __launch_bounds__(512) k_gemm1(const __nv_bfloat16* __restrict__ Ah,
                                               const __nv_bfloat16* __restrict__ Al,
                                               const __nv_bfloat16* __restrict__ Wh,
                                               const __nv_bfloat16* __restrict__ Wl,
                                               const float* __restrict__ bias,
                                               float* __restrict__ Cout,
                                               float* __restrict__ ssum, float* __restrict__ ssq) {
    constexpr int K = DD, NC = D2;
    __shared__ __align__(16) uint16_t sAh[128 * 40], sAl[128 * 40];
    __shared__ __align__(16) uint16_t sBh[128 * 40], sBl[128 * 40];
    int tid = threadIdx.x, lane = tid & 31, wid = tid >> 5;
    int bm = blockIdx.x * 128, bn = blockIdx.y * 128;
    if (blockIdx.x == 0 && blockIdx.y == 0 && tid < DD) {
        g_hsum[tid] = 0.f; g_hsumsq[tid] = 0.f;
    }
    const __nv_bfloat16* WhB = Wh + (size_t)bn * K;
    const __nv_bfloat16* WlB = Wl + (size_t)bn * K;

    float acc[2][4][4];
#pragma unroll
    for (int a = 0; a < 2; a++)
#pragma unroll
        for (int b = 0; b < 4; b++)
#pragma unroll
            for (int c = 0; c < 4; c++) acc[a][b][c] = 0.f;

    const int wr = (wid & 3) * 32, wc = (wid >> 2) * 32;
    const int mrow = (lane & 7) + ((lane >> 3) & 1) * 8;
    const int kof = (lane >> 4) * 8;
    const int lr = tid >> 2, lc8 = (tid & 3) * 8;
    const int gr = bm + lr;
    const bool av = gr < NN;

    for (int kc = 0; kc < K / 32; kc++) {
        uint4 zz = make_uint4(0, 0, 0, 0);
        uint4 vh = av ? *(const uint4*)(Ah + (size_t)gr * K + kc * 32 + lc8) : zz;
        uint4 vl = av ? *(const uint4*)(Al + (size_t)gr * K + kc * 32 + lc8) : zz;
        *(uint4*)&sAh[lr * 40 + lc8] = vh;
        *(uint4*)&sAl[lr * 40 + lc8] = vl;
        *(uint4*)&sBh[lr * 40 + lc8] = *(const uint4*)(WhB + (size_t)lr * K + kc * 32 + lc8);
        *(uint4*)&sBl[lr * 40 + lc8] = *(const uint4*)(WlB + (size_t)lr * K + kc * 32 + lc8);
        __syncthreads();
#pragma unroll
        for (int ks = 0; ks < 2; ks++) {
            uint32_t ah[2][4], al[2][4], bh[2][4], bl[2][4];
#pragma unroll
            for (int mt = 0; mt < 2; mt++) {
                LDSM4(ah[mt], smem_u32(&sAh[(wr + mt * 16 + mrow) * 40 + ks * 16 + kof]));
                LDSM4(al[mt], smem_u32(&sAl[(wr + mt * 16 + mrow) * 40 + ks * 16 + kof]));
            }
#pragma unroll
            for (int ng = 0; ng < 2; ng++) {
                LDSM4(bh[ng], smem_u32(&sBh[(wc + ng * 16 + mrow) * 40 + ks * 16 + kof]));
                LDSM4(bl[ng], smem_u32(&sBl[(wc + ng * 16 + mrow) * 40 + ks * 16 + kof]));
            }
#pragma unroll
            for (int mt = 0; mt < 2; mt++)
#pragma unroll
                for (int ng = 0; ng < 2; ng++)
#pragma unroll
                    for (int h = 0; h < 2; h++) {
                        float* a_ = acc[mt][ng * 2 + h];
                        mma16816(a_, ah[mt], bh[ng][h], bh[ng][h + 2]);
                        mma16816(a_, ah[mt], bl[ng][h], bl[ng][h + 2]);
                        mma16816(a_, al[mt], bh[ng][h], bh[ng][h + 2]);
                    }
        }
        __syncthreads();
    }

    // epilogue: +bias, write C fp32, column stats via shfl + atomics
    float sl[4][2], s2[4][2];
#pragma unroll
    for (int nt = 0; nt < 4; nt++) { sl[nt][0] = sl[nt][1] = s2[nt][0] = s2[nt][1] = 0.f; }
#pragma unroll
    for (int mt = 0; mt < 2; mt++) {
        int r0 = bm + wr + mt * 16 + (lane >> 2);
        int r1 = r0 + 8;
        bool v0 = r0 < NN, v1 = r1 < NN;
#pragma unroll
        for (int nt = 0; nt < 4; nt++) {
            int cg = bn + wc + nt * 8 + (lane & 3) * 2;
            float b0 = __ldg(&bias[cg]), b1 = __ldg(&bias[cg + 1]);
            float f00 = acc[mt][nt][0] + b0, f01 = acc[mt][nt][1] + b1;
            float f10 = acc[mt][nt][2] + b0, f11 = acc[mt][nt][3] + b1;
            if (v0) *(float2*)(Cout + (size_t)r0 * NC + cg) = make_float2(f00, f01);
            else { f00 = 0.f; f01 = 0.f; }
            if (v1) *(float2*)(Cout + (size_t)r1 * NC + cg) = make_float2(f10, f11);
            else { f10 = 0.f; f11 = 0.f; }
            sl[nt][0] += f00 + f10; sl[nt][1] += f01 + f11;
            s2[nt][0] += f00 * f00 + f10 * f10; s2[nt][1] += f01 * f01 + f11 * f11;
        }
    }
#pragma unroll
    for (int off = 4; off <= 16; off <<= 1)
#pragma unroll
        for (int nt = 0; nt < 4; nt++)
#pragma unroll
            for (int j = 0; j < 2; j++) {
                sl[nt][j] += __shfl_xor_sync(0xFFFFFFFF, sl[nt][j], off);
                s2[nt][j] += __shfl_xor_sync(0xFFFFFFFF, s2[nt][j], off);
            }
    if (lane < 4) {
#pragma unroll
        for (int nt = 0; nt < 4; nt++) {
            int cg = bn + wc + nt * 8 + lane * 2;
            atomicAdd(&ssum[cg], sl[nt][0]);
            atomicAdd(&ssum[cg + 1], sl[nt][1]);
            atomicAdd(&ssq[cg], s2[nt][0]);
            atomicAdd(&ssq[cg + 1], s2[nt][1]);
        }
    }
}

// ---------------- GEMM2: h = [h +] relu(bn(z)) @ W2^T (+bias); K=256, NC=128 ----------------
// BN(z) folded inline: smem zsc/zsh computed from raw z-stats at kernel start.
template <bool ACC>
__global__ void __launch_bounds__(512) k_gemm2(const float* __restrict__ Ain,
                                               const __nv_bfloat16* __restrict__ Wh,
                                               const __nv_bfloat16* __restrict__ Wl,
                                               const float* __restrict__ bias,
                                               const float* __restrict__ bng,
                                               const float* __restrict__ bnb,
                                               float* __restrict__ Cout,
                                               float* __restrict__ ssum, float* __restrict__ ssq) {
    constexpr int K = D2, NC = DD;
    __shared__ __align__(16) uint16_t sAh[128 * 40], sAl[128 * 40];
    __shared__ __align__(16) uint16_t sBh[128 * 40], sBl[128 * 40];
    __shared__ float szsc[D2], szsh[D2];
    int tid = threadIdx.x, lane = tid & 31, wid = tid >> 5;
    int bm = blockIdx.x * 128;
    if (tid < D2) {
        float mu = g_sum[tid] / (float)NN;
        float var = g_sumsq[tid] / (float)NN - mu * mu;
        float sc = rsqrtf(var + BN_EPS) * __ldg(&bng[tid]);
        szsc[tid] = sc;
        szsh[tid] = __ldg(&bnb[tid]) - mu * sc;
    }
    __syncthreads();

    float acc[2][4][4];
#pragma unroll
    for (int a = 0; a < 2; a++)
#pragma unroll
        for (int b = 0; b < 4; b++)
#pragma unroll
            for (int c = 0; c < 4; c++) acc[a][b][c] = 0.f;

    const int wr = (wid & 3) * 32, wc = (wid >> 2) * 32;
    const int mrow = (lane & 7) + ((lane >> 3) & 1) * 8;
    const int kof = (lane >> 4) * 8;
    const int lr = tid >> 2, lc8 = (tid & 3) * 8;

    for (int kc = 0; kc < K / 32; kc++) {
#pragma unroll
        for (int g = tid; g < 1024; g += 512) {
            int r = g >> 3, c4 = (g & 7) * 4;
            float4 v = make_float4(0.f, 0.f, 0.f, 0.f);
            int grr = bm + r;
            if (grr < NN) v = *(const float4*)(Ain + (size_t)grr * K + kc * 32 + c4);
            int cc = kc * 32 + c4;
            v.x = fmaxf(fmaf(v.x, szsc[cc + 0], szsh[cc + 0]), 0.f);
            v.y = fmaxf(fmaf(v.y, szsc[cc + 1], szsh[cc + 1]), 0.f);
            v.z = fmaxf(fmaf(v.z, szsc[cc + 2], szsh[cc + 2]), 0.f);
            v.w = fmaxf(fmaf(v.w, szsc[cc + 3], szsh[cc + 3]), 0.f);
            uint2 H, Lo;
            split4(v, H, Lo);
            *(uint2*)&sAh[r * 40 + c4] = H;
            *(uint2*)&sAl[r * 40 + c4] = Lo;
        }
        *(uint4*)&sBh[lr * 40 + lc8] = *(const uint4*)(Wh + (size_t)lr * K + kc * 32 + lc8);
        *(uint4*)&sBl[lr * 40 + lc8] = *(const uint4*)(Wl + (size_t)lr * K + kc * 32 + lc8);
        __syncthreads();
#pragma unroll
        for (int ks = 0; ks < 2; ks++) {
            uint32_t ah[2][4], al[2][4], bh[2][4], bl[2][4];
#pragma unroll
            for (int mt = 0; mt < 2; mt++) {
                LDSM4(ah[mt], smem_u32(&sAh[(wr + mt * 16 + mrow) * 40 + ks * 16 + kof]));
                LDSM4(al[mt], smem_u32(&sAl[(wr + mt * 16 + mrow) * 40 + ks * 16 + kof]));
            }
#pragma unroll
            for (int ng = 0; ng < 2; ng++) {
                LDSM4(bh[ng], smem_u32(&sBh[(wc + ng * 16 + mrow) * 40 + ks * 16 + kof]));
                LDSM4(bl[ng], smem_u32(&sBl[(wc + ng * 16 + mrow) * 40 + ks * 16 + kof]));
            }
#pragma unroll
            for (int mt = 0; mt < 2; mt++)
#pragma unroll
                for (int ng = 0; ng < 2; ng++)
#pragma unroll
                    for (int h = 0; h < 2; h++) {
                        float* a_ = acc[mt][ng * 2 + h];
                        mma16816(a_, ah[mt], bh[ng][h], bh[ng][h + 2]);
                        mma16816(a_, ah[mt], bl[ng][h], bl[ng][h + 2]);
                        mma16816(a_, al[mt], bh[ng][h], bh[ng][h + 2]);
                    }
        }
        __syncthreads();
    }

    // epilogue: +bias (+residual), write C, stats
    float sl[4][2], s2[4][2];
#pragma unroll
    for (int nt = 0; nt < 4; nt++) { sl[nt][0] = sl[nt][1] = s2[nt][0] = s2[nt][1] = 0.f; }
#pragma unroll
    for (int mt = 0; mt < 2; mt++) {
        int r0 = bm + wr + mt * 16 + (lane >> 2);
        int r1 = r0 + 8;
        bool v0 = r0 < NN, v1 = r1 < NN;
#pragma unroll
        for (int nt = 0; nt < 4; nt++) {
            int cg = wc + nt * 8 + (lane & 3) * 2;
            float b0 = __ldg(&bias[cg]), b1 = __ldg(&bias[cg + 1]);
            float f00 = acc[mt][nt][0] + b0, f01 = acc[mt][nt][1] + b1;
            float f10 = acc[mt][nt][2] + b0, f11 = acc[mt][nt][3] + b1;
            if (v0) {
                if (ACC) {
                    float2 o = *(float2*)(Cout + (size_t)r0 * NC + cg);
                    f00 += o.x; f01 += o.y;
                }
                *(float2*)(Cout + (size_t)r0 * NC + cg) = make_float2(f00, f01);
            } else { f00 = 0.f; f01 = 0.f; }
            if (v1) {
                if (ACC) {
                    float2 o = *(float2*)(Cout + (size_t)r1 * NC + cg);
                    f10 += o.x; f11 += o.y;
                }
                *(float2*)(Cout + (size_t)r1 * NC + cg) = make_float2(f10, f11);
            } else { f10 = 0.f; f11 = 0.f; }
            sl[nt][0] += f00 + f10; sl[nt][1] += f01 + f11;
            s2[nt][0] += f00 * f00 + f10 * f10; s2[nt][1] += f01 * f01 + f11 * f11;
        }
    }
#pragma unroll
    for (int off = 4; off <= 16; off <<= 1)
#pragma unroll
        for (int nt = 0; nt < 4; nt++)
#pragma unroll
            for (int j = 0; j < 2; j++) {
                sl[nt][j] += __shfl_xor_sync(0xFFFFFFFF, sl[nt][j], off);
                s2[nt][j] += __shfl_xor_sync(0xFFFFFFFF, s2[nt][j], off);
            }
    if (lane < 4) {
#pragma unroll
        for (int nt = 0; nt < 4; nt++) {
            int cg = wc + nt * 8 + lane * 2;
            atomicAdd(&ssum[cg], sl[nt][0]);
            atomicAdd(&ssum[cg + 1], sl[nt][1]);
            atomicAdd(&ssq[cg], s2[nt][0]);
            atomicAdd(&ssq[cg + 1], s2[nt][1]);
        }
    }
}

// ---------------- final pool + prediction ----------------
__global__ void k_pool(const int* __restrict__ batch) {
    int idx = blockIdx.x * blockDim.x + threadIdx.x;
    if (idx >= NN * DD) return;
    int i = idx >> 7, c = idx & 127;
    float y = fmaf(g_h[idx], g_hsc[c], g_hsh[c]);
    int b = __ldg(&batch[i]);
    atomicAdd(&g_pool[b * DD + c], y);
    if (c == 0) atomicAdd(&g_cnt[b], 1.f);
}
__global__ void k_pred(const float* __restrict__ pw, const float* __restrict__ pb,
                       float* __restrict__ out) {   // <<<BB,128>>>
    __shared__ float red[128];
    int b = blockIdx.x, d = threadIdx.x;
    float g = g_pool[b * DD + d] / fmaxf(g_cnt[b], 1.f);
    for (int t = 0; t < TT; t++) {
        red[d] = g * __ldg(&pw[d * TT + t]);
        __syncthreads();
        for (int off = 64; off > 0; off >>= 1) {
            if (d < off) red[d] += red[d + off];
            __syncthreads();
        }
        if (d == 0) out[b * TT + t] = red[0] + __ldg(&pb[t]);
        __syncthreads();
    }
}

// ---------------- launch ----------------
extern "C" void kernel_launch(void* const* d_in, const int* in_sizes, int n_in,
                              void* d_out, int out_size) {
    (void)in_sizes; (void)n_in; (void)out_size;
    const int*   x      = (const int*)d_in[0];
    const int*   eidx   = (const int*)d_in[1];
    const int*   eattr  = (const int*)d_in[2];
    const int*   batch  = (const int*)d_in[3];
    const int*   aoff   = (const int*)d_in[4];
    const int*   boff   = (const int*)d_in[5];
    const float* atab   = (const float*)d_in[6];
    const float* btab   = (const float*)d_in[7];
    const float* ngamma = (const float*)d_in[8];
    const float* nbeta  = (const float*)d_in[9];
    const float* tarr   = (const float*)d_in[10];
    const float* w1     = (const float*)d_in[11];
    const float* b1     = (const float*)d_in[12];
    const float* bng    = (const float*)d_in[13];
    const float* bnb    = (const float*)d_in[14];
    const float* w2     = (const float*)d_in[15];
    const float* b2     = (const float*)d_in[16];
    const float* pw     = (const float*)d_in[17];
    const float* pb     = (const float*)d_in[18];
    float* out = (float*)d_out;

    const int* src = eidx;
    const int* dst = eidx + EE;

    float *p_h, *p_z, *p_sum, *p_sumsq, *p_hsum, *p_hsumsq;
    __nv_bfloat16 *p_w1h, *p_w1l, *p_w2h, *p_w2l, *p_xh, *p_xl;
    cudaGetSymbolAddress((void**)&p_h, g_h);
    cudaGetSymbolAddress((void**)&p_z, g_z);
    cudaGetSymbolAddress((void**)&p_sum, g_sum);
    cudaGetSymbolAddress((void**)&p_sumsq, g_sumsq);
    cudaGetSymbolAddress((void**)&p_hsum, g_hsum);
    cudaGetSymbolAddress((void**)&p_hsumsq, g_hsumsq);
    cudaGetSymbolAddress((void**)&p_w1h, g_w1h);
    cudaGetSymbolAddress((void**)&p_w1l, g_w1l);
    cudaGetSymbolAddress((void**)&p_w2h, g_w2h);
    cudaGetSymbolAddress((void**)&p_w2l, g_w2l);
    cudaGetSymbolAddress((void**)&p_xh, g_xh);
    cudaGetSymbolAddress((void**)&p_xl, g_xl);

    // ---- setup: CSR build + encoders + weight prep (zeros fused into one kernel) ----
    k_zero_all<<<(BB * DD + 255) / 256, 256>>>();
    k_hist<<<(EE + 255) / 256, 256>>>(dst);
    k_scan1<<<NSB, 1024>>>();
    k_scan2<<<1, 32>>>();
    k_scan3<<<(NN + 255) / 256, 256>>>();
    k_scatter<<<(EE + 255) / 256, 256>>>(src, dst, eattr);
    k_atom<<<(NN * DD + 255) / 256, 256>>>(x, aoff, atab);
    k_btab<<<(NCOMBO * DD + 255) / 256, 256>>>(boff, btab);
    k_wprep1<<<(LL * D2 * DD + 255) / 256, 256>>>(w1);
    k_wprep2<<<(LL * DD * D2 + 255) / 256, 256>>>(w2);

    // ---- 7 layers, 3 launches each ----
    for (int l = 0; l < LL; l++) {
        k_aggr<<<NN / 2, 256>>>(ngamma + l * DD, nbeta + l * DD, tarr, l, l > 0 ? 1 : 0);
        k_gemm1<<<dim3(MT, 2), 512>>>(
            p_xh, p_xl, p_w1h + (size_t)l * D2 * DD, p_w1l + (size_t)l * D2 * DD,
            b1 + l * D2, p_z, p_sum, p_sumsq);
        if (l == 0)
            k_gemm2<false><<<MT, 512>>>(
                p_z, p_w2h + (size_t)l * DD * D2, p_w2l + (size_t)l * DD * D2,
                b2 + l * DD, bng + l * D2, bnb + l * D2, p_h, p_hsum, p_hsumsq);
        else
            k_gemm2<true><<<MT, 512>>>(
                p_z, p_w2h + (size_t)l * DD * D2, p_w2l + (size_t)l * DD * D2,
                b2 + l * DD, bng + l * D2, bnb + l * D2, p_h, p_hsum, p_hsumsq);
    }

    // ---- final norm + pool + predict ----
    k_bnfin_h<<<1, 128>>>(ngamma, nbeta);
    k_pool<<<(NN * DD + 255) / 256, 256>>>(batch);
    k_pred<<<BB, 128>>>(pw, pb, out);
}

// round 16
// speedup vs baseline: 1.0572x; 1.0572x over previous
#include <cuda_runtime.h>
#include <cuda_bf16.h>
#include <cuda_fp16.h>
#include <stdint.h>
#include <math.h>

#define NN 50000
#define EE 600000
#define DD 128
#define D2 256
#define LL 7
#define BB 512
#define TT 10
#define BN_EPS 1e-5f
#define MSG_EPS 1e-7f
#define MT 391    // ceil(50000/128)
#define NSB 49    // ceil(50000/1024) scan blocks
#define NCOMBO 60 // 5*6*2 bond-attr combos

// ---------------- scratch ----------------
__device__ float g_h[NN * DD];
__device__ __half g_cin[NN * DD];                      // fp16 relu(bn(h)) (or h at l=0)
__device__ __nv_bfloat16 g_xh[NN * DD], g_xl[NN * DD]; // conv out, bf16 split
__device__ float g_z[NN * D2];
__device__ __half g_bt16[NCOMBO * DD];                 // bond combo table (fp16), L1-resident
__device__ uint8_t g_ecid[EE];                         // per sorted edge: combo id
__device__ int   g_deg[NN], g_rowptr[NN + 1], g_cursor[NN], g_srcs[EE];
__device__ int   g_bsum[64], g_boff[64];
__device__ float g_sum[D2], g_sumsq[D2];     // z stats
__device__ float g_hsum[DD], g_hsumsq[DD];   // h stats
__device__ float g_zsc[D2], g_zsh[D2];       // folded BN(z)
__device__ float g_hsc[DD], g_hsh[DD];       // folded BN(h)
__device__ __nv_bfloat16 g_w1h[LL * D2 * DD], g_w1l[LL * D2 * DD];  // [l][n=256][k=128]
__device__ __nv_bfloat16 g_w2h[LL * DD * D2], g_w2l[LL * DD * D2];  // [l][n=128][k=256]
__device__ float g_pool[BB * DD];
__device__ float g_cnt[BB];

// ---------------- helpers ----------------
__device__ __forceinline__ uint32_t smem_u32(const void* p) {
    uint32_t a;
    asm("{ .reg .u64 t; cvta.to.shared.u64 t, %1; cvt.u32.u64 %0, t; }" : "=r"(a) : "l"(p));
    return a;
}
#define LDSM4(R, addr)                                                                      \
    asm volatile("ldmatrix.sync.aligned.m8n8.x4.shared.b16 {%0,%1,%2,%3}, [%4];"            \
        : "=r"((R)[0]), "=r"((R)[1]), "=r"((R)[2]), "=r"((R)[3]) : "r"(addr))

__device__ __forceinline__ void mma16816(float* c, const uint32_t* a, uint32_t b0, uint32_t b1) {
    asm volatile("mma.sync.aligned.m16n8k16.row.col.f32.bf16.bf16.f32 "
        "{%0,%1,%2,%3},{%4,%5,%6,%7},{%8,%9},{%0,%1,%2,%3};"
        : "+f"(c[0]), "+f"(c[1]), "+f"(c[2]), "+f"(c[3])
        : "r"(a[0]), "r"(a[1]), "r"(a[2]), "r"(a[3]), "r"(b0), "r"(b1));
}

__device__ __forceinline__ void split4(float4 v, uint2& H, uint2& Lo) {
    __nv_bfloat16 a = __float2bfloat16(v.x), b = __float2bfloat16(v.y);
    __nv_bfloat16 c = __float2bfloat16(v.z), d = __float2bfloat16(v.w);
    __nv_bfloat162 h0 = __halves2bfloat162(a, b), h1 = __halves2bfloat162(c, d);
    H.x = *(uint32_t*)&h0; H.y = *(uint32_t*)&h1;
    __nv_bfloat162 l0 = __floats2bfloat162_rn(v.x - __bfloat162float(a), v.y - __bfloat162float(b));
    __nv_bfloat162 l1 = __floats2bfloat162_rn(v.z - __bfloat162float(c), v.w - __bfloat162float(d));
    Lo.x = *(uint32_t*)&l0; Lo.y = *(uint32_t*)&l1;
}

// ---------------- utility kernels ----------------
__global__ void k_zero_deg() {
    int i = blockIdx.x * blockDim.x + threadIdx.x;
    if (i < NN) g_deg[i] = 0;
}
__global__ void k_zero_stats() {   // <<<1,256>>>
    int c = threadIdx.x;
    g_sum[c] = 0.f; g_sumsq[c] = 0.f;
}
__global__ void k_zero_pool() {
    int i = blockIdx.x * blockDim.x + threadIdx.x;
    if (i < BB * DD) g_pool[i] = 0.f;
    if (i < BB) g_cnt[i] = 0.f;
}
__global__ void k_hist(const int* __restrict__ dst) {
    int e = blockIdx.x * blockDim.x + threadIdx.x;
    if (e < EE) atomicAdd(&g_deg[dst[e]], 1);
}
// parallel scan, 3 stages
__global__ void k_scan1() {   // <<<NSB,1024>>>
    __shared__ int sh[1024];
    int tid = threadIdx.x;
    int gid = blockIdx.x * 1024 + tid;
    int v = (gid < NN) ? g_deg[gid] : 0;
    sh[tid] = v;
    __syncthreads();
#pragma unroll
    for (int off = 1; off < 1024; off <<= 1) {
        int x = (tid >= off) ? sh[tid - off] : 0;
        __syncthreads();
        sh[tid] += x;
        __syncthreads();
    }
    if (gid < NN) g_rowptr[gid] = sh[tid] - v;
    if (tid == 1023) g_bsum[blockIdx.x] = sh[1023];
}
__global__ void k_scan2() {   // <<<1,32>>>
    if (threadIdx.x == 0) {
        int c = 0;
        for (int i = 0; i < NSB; i++) { g_boff[i] = c; c += g_bsum[i]; }
        g_rowptr[NN] = c;
    }
}
__global__ void k_scan3() {
    int i = blockIdx.x * blockDim.x + threadIdx.x;
    if (i < NN) {
        int r = g_rowptr[i] + g_boff[i >> 10];
        g_rowptr[i] = r;
        g_cursor[i] = r;
    }
}
__global__ void k_scatter(const int* __restrict__ src, const int* __restrict__ dst,
                          const int* __restrict__ eattr) {
    int e = blockIdx.x * blockDim.x + threadIdx.x;
    if (e < EE) {
        int p = atomicAdd(&g_cursor[dst[e]], 1);
        g_srcs[p] = src[e];
        int a0 = __ldg(&eattr[e * 3 + 0]);
        int a1 = __ldg(&eattr[e * 3 + 1]);
        int a2 = __ldg(&eattr[e * 3 + 2]);
        g_ecid[p] = (uint8_t)(a0 * 12 + a1 * 2 + a2);
    }
}
__global__ void k_atom(const int* __restrict__ x, const int* __restrict__ aoff,
                       const float* __restrict__ atab) {
    int idx = blockIdx.x * blockDim.x + threadIdx.x;
    if (idx >= NN * DD) return;
    int i = idx >> 7, d = idx & 127;
    float acc = 0.f;
#pragma unroll
    for (int f = 0; f < 9; f++) {
        int row = __ldg(&x[i * 9 + f]) + __ldg(&aoff[f]);
        acc += __ldg(&atab[row * DD + d]);
    }
    g_h[idx] = acc;
}
__global__ void k_btab(const int* __restrict__ boff, const float* __restrict__ btab) {
    int idx = blockIdx.x * blockDim.x + threadIdx.x;
    if (idx >= NCOMBO * DD) return;
    int cid = idx >> 7, d = idx & 127;
    int a0 = cid / 12, a1 = (cid % 12) / 2, a2 = cid & 1;
    float acc = __ldg(&btab[(a0 + __ldg(&boff[0])) * DD + d]) +
                __ldg(&btab[(a1 + __ldg(&boff[1])) * DD + d]) +
                __ldg(&btab[(a2 + __ldg(&boff[2])) * DD + d]);
    g_bt16[idx] = __float2half_rn(acc);
}
__global__ void k_wprep1(const float* __restrict__ w1) {
    int idx = blockIdx.x * blockDim.x + threadIdx.x;
    if (idx >= LL * D2 * DD) return;
    int l = idx / (D2 * DD), rem = idx % (D2 * DD);
    int n = rem / DD, k = rem % DD;
    float v = __ldg(&w1[(size_t)l * DD * D2 + k * D2 + n]);
    __nv_bfloat16 hi = __float2bfloat16(v);
    g_w1h[idx] = hi;
    g_w1l[idx] = __float2bfloat16(v - __bfloat162float(hi));
}
__global__ void k_wprep2(const float* __restrict__ w2) {
    int idx = blockIdx.x * blockDim.x + threadIdx.x;
    if (idx >= LL * DD * D2) return;
    int l = idx / (DD * D2), rem = idx % (DD * D2);
    int n = rem / D2, k = rem % D2;
    float v = __ldg(&w2[(size_t)l * D2 * DD + k * DD + n]);
    __nv_bfloat16 hi = __float2bfloat16(v);
    g_w2h[idx] = hi;
    g_w2l[idx] = __float2bfloat16(v - __bfloat162float(hi));
}

// BN finalize. bnfin_z also zeros h-stats; bnfin_h also zeros z-stats.
__global__ void k_bnfin_z(const float* __restrict__ bng, const float* __restrict__ bnb) { // <<<1,256>>>
    int c = threadIdx.x;
    float mu = g_sum[c] / (float)NN;
    float var = g_sumsq[c] / (float)NN - mu * mu;
    float sc = rsqrtf(var + BN_EPS) * __ldg(&bng[c]);
    g_zsc[c] = sc;
    g_zsh[c] = __ldg(&bnb[c]) - mu * sc;
    if (c < DD) { g_hsum[c] = 0.f; g_hsumsq[c] = 0.f; }
}
__global__ void k_bnfin_h(const float* __restrict__ gamma, const float* __restrict__ beta) { // <<<1,256>>>
    int c = threadIdx.x;
    if (c < DD) {
        float mu = g_hsum[c] / (float)NN;
        float var = g_hsumsq[c] / (float)NN - mu * mu;
        float sc = rsqrtf(var + BN_EPS) * __ldg(&gamma[c]);
        g_hsc[c] = sc;
        g_hsh[c] = __ldg(&beta[c]) - mu * sc;
    }
    g_sum[c] = 0.f; g_sumsq[c] = 0.f;
}

// prenorm: cin = fp16(relu(bn(h))) for l>0, fp16(h) for l=0. 2 dims/thread.
__global__ void k_prenorm(int use_bn) {
    int idx = blockIdx.x * blockDim.x + threadIdx.x;   // over NN*DD/2
    if (idx >= NN * DD / 2) return;
    int c2 = (idx & 63) * 2;
    float2 v = *(const float2*)(g_h + (size_t)idx * 2);
    if (use_bn) {
        v.x = fmaxf(fmaf(v.x, g_hsc[c2], g_hsh[c2]), 0.f);
        v.y = fmaxf(fmaf(v.y, g_hsc[c2 + 1], g_hsh[c2 + 1]), 0.f);
    }
    *(__half2*)(g_cin + (size_t)idx * 2) = __floats2half2_rn(v.x, v.y);
}

// ---------------- aggregation: 4 edge-groups x 32 lanes x 4 fp16 dims ----------------
// messages gather fp16 cin (256B/edge); self term fp32 from g_h (BN inline).
__global__ void __launch_bounds__(128) k_aggr(const float* __restrict__ tarr, int layer, int use_bn) {
    __shared__ float4 rse[4][32], rsn[4][32];
    int tid = threadIdx.x, lane = tid & 31, grp = tid >> 5;
    int u = blockIdx.x;
    int d4 = lane << 2;
    int beg = g_rowptr[u];
    int deg = g_rowptr[u + 1] - beg;
    float tl = __ldg(&tarr[layer]);
    float4 se = make_float4(0.f, 0.f, 0.f, 0.f);
    float4 sn = make_float4(0.f, 0.f, 0.f, 0.f);
    for (int j = grp; j < deg; j += 4) {
        int s = __ldg(&g_srcs[beg + j]);
        int cid = (int)__ldg(&g_ecid[beg + j]);
        uint2 cu = __ldg((const uint2*)(g_cin + (size_t)s * DD + d4));
        float2 c01 = __half22float2(*(__half2*)&cu.x);
        float2 c23 = __half22float2(*(__half2*)&cu.y);
        uint2 eu = *(const uint2*)(g_bt16 + cid * DD + d4);
        float2 e01 = __half22float2(*(__half2*)&eu.x);
        float2 e23 = __half22float2(*(__half2*)&eu.y);
        float m0 = fmaxf(c01.x + e01.x, 0.f) + MSG_EPS;
        float m1 = fmaxf(c01.y + e01.y, 0.f) + MSG_EPS;
        float m2 = fmaxf(c23.x + e23.x, 0.f) + MSG_EPS;
        float m3 = fmaxf(c23.y + e23.y, 0.f) + MSG_EPS;
        float e0 = __expf(m0 * tl), e1 = __expf(m1 * tl);
        float e2 = __expf(m2 * tl), e3 = __expf(m3 * tl);
        se.x += e0; se.y += e1; se.z += e2; se.w += e3;
        sn.x = fmaf(m0, e0, sn.x); sn.y = fmaf(m1, e1, sn.y);
        sn.z = fmaf(m2, e2, sn.z); sn.w = fmaf(m3, e3, sn.w);
    }
    rse[grp][lane] = se;
    rsn[grp][lane] = sn;
    __syncthreads();
    if (grp == 0) {
#pragma unroll
        for (int g = 1; g < 4; g++) {
            float4 a = rse[g][lane], b = rsn[g][lane];
            se.x += a.x; se.y += a.y; se.z += a.z; se.w += a.w;
            sn.x += b.x; sn.y += b.y; sn.z += b.z; sn.w += b.w;
        }
        float4 hv = *(const float4*)(g_h + (size_t)u * DD + d4);
        float4 v;
        if (use_bn) {
            float4 sc4 = *(const float4*)&g_hsc[d4];
            float4 sh4 = *(const float4*)&g_hsh[d4];
            v.x = fmaxf(fmaf(hv.x, sc4.x, sh4.x), 0.f);
            v.y = fmaxf(fmaf(hv.y, sc4.y, sh4.y), 0.f);
            v.z = fmaxf(fmaf(hv.z, sc4.z, sh4.z), 0.f);
            v.w = fmaxf(fmaf(hv.w, sc4.w, sh4.w), 0.f);
        } else {
            v = hv;
        }
        if (deg > 0) {
            v.x += sn.x / (se.x + 1e-16f);
            v.y += sn.y / (se.y + 1e-16f);
            v.z += sn.z / (se.z + 1e-16f);
            v.w += sn.w / (se.w + 1e-16f);
        }
        uint2 H, Lo;
        split4(v, H, Lo);
        *(uint2*)(g_xh + (size_t)u * DD + d4) = H;
        *(uint2*)(g_xl + (size_t)u * DD + d4) = Lo;
    }
}

// ---------------- GEMM1: z = x @ W1^T (+bias); A bf16 split, K=128, NC=256 ----------------
__global__ void __launch_bounds__(512) k_gemm1(const __nv_bfloat16* __restrict__ Ah,
                                               const __nv_bfloat16* __restrict__ Al,
                                               const __nv_bfloat16* __restrict__ Wh,
                                               const __nv_bfloat16* __restrict__ Wl,
                                               const float* __restrict__ bias,
                                               float* __restrict__ Cout,
                                               float* __restrict__ ssum, float* __restrict__ ssq) {
    constexpr int K = DD, NC = D2;
    __shared__ __align__(16) uint16_t sAh[128 * 40], sAl[128 * 40];
    __shared__ __align__(16) uint16_t sBh[128 * 40], sBl[128 * 40];
    int tid = threadIdx.x, lane = tid & 31, wid = tid >> 5;
    int bm = blockIdx.x * 128, bn = blockIdx.y * 128;
    const __nv_bfloat16* WhB = Wh + (size_t)bn * K;
    const __nv_bfloat16* WlB = Wl + (size_t)bn * K;

    float acc[2][4][4];
#pragma unroll
    for (int a = 0; a < 2; a++)
#pragma unroll
        for (int b = 0; b < 4; b++)
#pragma unroll
            for (int c = 0; c < 4; c++) acc[a][b][c] = 0.f;

    const int wr = (wid & 3) * 32, wc = (wid >> 2) * 32;
    const int mrow = (lane & 7) + ((lane >> 3) & 1) * 8;
    const int kof = (lane >> 4) * 8;
    const int lr = tid >> 2, lc8 = (tid & 3) * 8;
    const int gr = bm + lr;
    const bool av = gr < NN;

    for (int kc = 0; kc < K / 32; kc++) {
        uint4 zz = make_uint4(0, 0, 0, 0);
        uint4 vh = av ? *(const uint4*)(Ah + (size_t)gr * K + kc * 32 + lc8) : zz;
        uint4 vl = av ? *(const uint4*)(Al + (size_t)gr * K + kc * 32 + lc8) : zz;
        *(uint4*)&sAh[lr * 40 + lc8] = vh;
        *(uint4*)&sAl[lr * 40 + lc8] = vl;
        *(uint4*)&sBh[lr * 40 + lc8] = *(const uint4*)(WhB + (size_t)lr * K + kc * 32 + lc8);
        *(uint4*)&sBl[lr * 40 + lc8] = *(const uint4*)(WlB + (size_t)lr * K + kc * 32 + lc8);
        __syncthreads();
#pragma unroll
        for (int ks = 0; ks < 2; ks++) {
            uint32_t ah[2][4], al[2][4], bh[2][4], bl[2][4];
#pragma unroll
            for (int mt = 0; mt < 2; mt++) {
                LDSM4(ah[mt], smem_u32(&sAh[(wr + mt * 16 + mrow) * 40 + ks * 16 + kof]));
                LDSM4(al[mt], smem_u32(&sAl[(wr + mt * 16 + mrow) * 40 + ks * 16 + kof]));
            }
#pragma unroll
            for (int ng = 0; ng < 2; ng++) {
                LDSM4(bh[ng], smem_u32(&sBh[(wc + ng * 16 + mrow) * 40 + ks * 16 + kof]));
                LDSM4(bl[ng], smem_u32(&sBl[(wc + ng * 16 + mrow) * 40 + ks * 16 + kof]));
            }
#pragma unroll
            for (int mt = 0; mt < 2; mt++)
#pragma unroll
                for (int ng = 0; ng < 2; ng++)
#pragma unroll
                    for (int h = 0; h < 2; h++) {
                        float* a_ = acc[mt][ng * 2 + h];
                        mma16816(a_, ah[mt], bh[ng][h], bh[ng][h + 2]);
                        mma16816(a_, ah[mt], bl[ng][h], bl[ng][h + 2]);
                        mma16816(a_, al[mt], bh[ng][h], bh[ng][h + 2]);
                    }
        }
        __syncthreads();
    }

    // epilogue: +bias, write C fp32, column stats via shfl + atomics
    float sl[4][2], s2[4][2];
#pragma unroll
    for (int nt = 0; nt < 4; nt++) { sl[nt][0] = sl[nt][1] = s2[nt][0] = s2[nt][1] = 0.f; }
#pragma unroll
    for (int mt = 0; mt < 2; mt++) {
        int r0 = bm + wr + mt * 16 + (lane >> 2);
        int r1 = r0 + 8;
        bool v0 = r0 < NN, v1 = r1 < NN;
#pragma unroll
        for (int nt = 0; nt < 4; nt++) {
            int cg = bn + wc + nt * 8 + (lane & 3) * 2;
            float b0 = __ldg(&bias[cg]), b1 = __ldg(&bias[cg + 1]);
            float f00 = acc[mt][nt][0] + b0, f01 = acc[mt][nt][1] + b1;
            float f10 = acc[mt][nt][2] + b0, f11 = acc[mt][nt][3] + b1;
            if (v0) *(float2*)(Cout + (size_t)r0 * NC + cg) = make_float2(f00, f01);
            else { f00 = 0.f; f01 = 0.f; }
            if (v1) *(float2*)(Cout + (size_t)r1 * NC + cg) = make_float2(f10, f11);
            else { f10 = 0.f; f11 = 0.f; }
            sl[nt][0] += f00 + f10; sl[nt][1] += f01 + f11;
            s2[nt][0] += f00 * f00 + f10 * f10; s2[nt][1] += f01 * f01 + f11 * f11;
        }
    }
#pragma unroll
    for (int off = 4; off <= 16; off <<= 1)
#pragma unroll
        for (int nt = 0; nt < 4; nt++)
#pragma unroll
            for (int j = 0; j < 2; j++) {
                sl[nt][j] += __shfl_xor_sync(0xFFFFFFFF, sl[nt][j], off);
                s2[nt][j] += __shfl_xor_sync(0xFFFFFFFF, s2[nt][j], off);
            }
    if (lane < 4) {
#pragma unroll
        for (int nt = 0; nt < 4; nt++) {
            int cg = bn + wc + nt * 8 + lane * 2;
            atomicAdd(&ssum[cg], sl[nt][0]);
            atomicAdd(&ssum[cg + 1], sl[nt][1]);
            atomicAdd(&ssq[cg], s2[nt][0]);
            atomicAdd(&ssq[cg + 1], s2[nt][1]);
        }
    }
}

// ---------------- GEMM2: h = [h +] relu(bn(z)) @ W2^T (+bias); K=256, NC=128 ----------------
template <bool ACC>
__global__ void __launch_bounds__(512) k_gemm2(const float* __restrict__ Ain,
                                               const __nv_bfloat16* __restrict__ Wh,
                                               const __nv_bfloat16* __restrict__ Wl,
                                               const float* __restrict__ bias,
                                               float* __restrict__ Cout,
                                               float* __restrict__ ssum, float* __restrict__ ssq) {
    constexpr int K = D2, NC = DD;
    __shared__ __align__(16) uint16_t sAh[128 * 40], sAl[128 * 40];
    __shared__ __align__(16) uint16_t sBh[128 * 40], sBl[128 * 40];
    int tid = threadIdx.x, lane = tid & 31, wid = tid >> 5;
    int bm = blockIdx.x * 128;

    float acc[2][4][4];
#pragma unroll
    for (int a = 0; a < 2; a++)
#pragma unroll
        for (int b = 0; b < 4; b++)
#pragma unroll
            for (int c = 0; c < 4; c++) acc[a][b][c] = 0.f;

    const int wr = (wid & 3) * 32, wc = (wid >> 2) * 32;
    const int mrow = (lane & 7) + ((lane >> 3) & 1) * 8;
    const int kof = (lane >> 4) * 8;
    const int lr = tid >> 2, lc8 = (tid & 3) * 8;

    for (int kc = 0; kc < K / 32; kc++) {
#pragma unroll
        for (int g = tid; g < 1024; g += 512) {
            int r = g >> 3, c4 = (g & 7) * 4;
            float4 v = make_float4(0.f, 0.f, 0.f, 0.f);
            int grr = bm + r;
            if (grr < NN) v = *(const float4*)(Ain + (size_t)grr * K + kc * 32 + c4);
            int cc = kc * 32 + c4;
            v.x = fmaxf(fmaf(v.x, g_zsc[cc + 0], g_zsh[cc + 0]), 0.f);
            v.y = fmaxf(fmaf(v.y, g_zsc[cc + 1], g_zsh[cc + 1]), 0.f);
            v.z = fmaxf(fmaf(v.z, g_zsc[cc + 2], g_zsh[cc + 2]), 0.f);
            v.w = fmaxf(fmaf(v.w, g_zsc[cc + 3], g_zsh[cc + 3]), 0.f);
            uint2 H, Lo;
            split4(v, H, Lo);
            *(uint2*)&sAh[r * 40 + c4] = H;
            *(uint2*)&sAl[r * 40 + c4] = Lo;
        }
        *(uint4*)&sBh[lr * 40 + lc8] = *(const uint4*)(Wh + (size_t)lr * K + kc * 32 + lc8);
        *(uint4*)&sBl[lr * 40 + lc8] = *(const uint4*)(Wl + (size_t)lr * K + kc * 32 + lc8);
        __syncthreads();
#pragma unroll
        for (int ks = 0; ks < 2; ks++) {
            uint32_t ah[2][4], al[2][4], bh[2][4], bl[2][4];
#pragma unroll
            for (int mt = 0; mt < 2; mt++) {
                LDSM4(ah[mt], smem_u32(&sAh[(wr + mt * 16 + mrow) * 40 + ks * 16 + kof]));
                LDSM4(al[mt], smem_u32(&sAl[(wr + mt * 16 + mrow) * 40 + ks * 16 + kof]));
            }
#pragma unroll
            for (int ng = 0; ng < 2; ng++) {
                LDSM4(bh[ng], smem_u32(&sBh[(wc + ng * 16 + mrow) * 40 + ks * 16 + kof]));
                LDSM4(bl[ng], smem_u32(&sBl[(wc + ng * 16 + mrow) * 40 + ks * 16 + kof]));
            }
#pragma unroll
            for (int mt = 0; mt < 2; mt++)
#pragma unroll
                for (int ng = 0; ng < 2; ng++)
#pragma unroll
                    for (int h = 0; h < 2; h++) {
                        float* a_ = acc[mt][ng * 2 + h];
                        mma16816(a_, ah[mt], bh[ng][h], bh[ng][h + 2]);
                        mma16816(a_, ah[mt], bl[ng][h], bl[ng][h + 2]);
                        mma16816(a_, al[mt], bh[ng][h], bh[ng][h + 2]);
                    }
        }
        __syncthreads();
    }

    // epilogue: +bias (+residual), write C, stats
    float sl[4][2], s2[4][2];
#pragma unroll
    for (int nt = 0; nt < 4; nt++) { sl[nt][0] = sl[nt][1] = s2[nt][0] = s2[nt][1] = 0.f; }
#pragma unroll
    for (int mt = 0; mt < 2; mt++) {
        int r0 = bm + wr + mt * 16 + (lane >> 2);
        int r1 = r0 + 8;
        bool v0 = r0 < NN, v1 = r1 < NN;
#pragma unroll
        for (int nt = 0; nt < 4; nt++) {
            int cg = wc + nt * 8 + (lane & 3) * 2;
            float b0 = __ldg(&bias[cg]), b1 = __ldg(&bias[cg + 1]);
            float f00 = acc[mt][nt][0] + b0, f01 = acc[mt][nt][1] + b1;
            float f10 = acc[mt][nt][2] + b0, f11 = acc[mt][nt][3] + b1;
            if (v0) {
                if (ACC) {
                    float2 o = *(float2*)(Cout + (size_t)r0 * NC + cg);
                    f00 += o.x; f01 += o.y;
                }
                *(float2*)(Cout + (size_t)r0 * NC + cg) = make_float2(f00, f01);
            } else { f00 = 0.f; f01 = 0.f; }
            if (v1) {
                if (ACC) {
                    float2 o = *(float2*)(Cout + (size_t)r1 * NC + cg);
                    f10 += o.x; f11 += o.y;
                }
                *(float2*)(Cout + (size_t)r1 * NC + cg) = make_float2(f10, f11);
            } else { f10 = 0.f; f11 = 0.f; }
            sl[nt][0] += f00 + f10; sl[nt][1] += f01 + f11;
            s2[nt][0] += f00 * f00 + f10 * f10; s2[nt][1] += f01 * f01 + f11 * f11;
        }
    }
#pragma unroll
    for (int off = 4; off <= 16; off <<= 1)
#pragma unroll
        for (int nt = 0; nt < 4; nt++)
#pragma unroll
            for (int j = 0; j < 2; j++) {
                sl[nt][j] += __shfl_xor_sync(0xFFFFFFFF, sl[nt][j], off);
                s2[nt][j] += __shfl_xor_sync(0xFFFFFFFF, s2[nt][j], off);
            }
    if (lane < 4) {
#pragma unroll
        for (int nt = 0; nt < 4; nt++) {
            int cg = wc + nt * 8 + lane * 2;
            atomicAdd(&ssum[cg], sl[nt][0]);
            atomicAdd(&ssum[cg + 1], sl[nt][1]);
            atomicAdd(&ssq[cg], s2[nt][0]);
            atomicAdd(&ssq[cg + 1], s2[nt][1]);
        }
    }
}

// ---------------- final pool + prediction ----------------
__global__ void k_pool(const int* __restrict__ batch) {
    int idx = blockIdx.x * blockDim.x + threadIdx.x;
    if (idx >= NN * DD) return;
    int i = idx >> 7, c = idx & 127;
    float y = fmaf(g_h[idx], g_hsc[c], g_hsh[c]);
    int b = __ldg(&batch[i]);
    atomicAdd(&g_pool[b * DD + c], y);
    if (c == 0) atomicAdd(&g_cnt[b], 1.f);
}
__global__ void k_pred(const float* __restrict__ pw, const float* __restrict__ pb,
                       float* __restrict__ out) {   // <<<BB,128>>>
    __shared__ float red[128];
    int b = blockIdx.x, d = threadIdx.x;
    float g = g_pool[b * DD + d] / fmaxf(g_cnt[b], 1.f);
    for (int t = 0; t < TT; t++) {
        red[d] = g * __ldg(&pw[d * TT + t]);
        __syncthreads();
        for (int off = 64; off > 0; off >>= 1) {
            if (d < off) red[d] += red[d + off];
            __syncthreads();
        }
        if (d == 0) out[b * TT + t] = red[0] + __ldg(&pb[t]);
        __syncthreads();
    }
}

// ---------------- launch ----------------
extern "C" void kernel_launch(void* const* d_in, const int* in_sizes, int n_in,
                              void* d_out, int out_size) {
    (void)in_sizes; (void)n_in; (void)out_size;
    const int*   x      = (const int*)d_in[0];
    const int*   eidx   = (const int*)d_in[1];
    const int*   eattr  = (const int*)d_in[2];
    const int*   batch  = (const int*)d_in[3];
    const int*   aoff   = (const int*)d_in[4];
    const int*   boff   = (const int*)d_in[5];
    const float* atab   = (const float*)d_in[6];
    const float* btab   = (const float*)d_in[7];
    const float* ngamma = (const float*)d_in[8];
    const float* nbeta  = (const float*)d_in[9];
    const float* tarr   = (const float*)d_in[10];
    const float* w1     = (const float*)d_in[11];
    const float* b1     = (const float*)d_in[12];
    const float* bng    = (const float*)d_in[13];
    const float* bnb    = (const float*)d_in[14];
    const float* w2     = (const float*)d_in[15];
    const float* b2     = (const float*)d_in[16];
    const float* pw     = (const float*)d_in[17];
    const float* pb     = (const float*)d_in[18];
    float* out = (float*)d_out;

    const int* src = eidx;
    const int* dst = eidx + EE;

    float *p_h, *p_z, *p_sum, *p_sumsq, *p_hsum, *p_hsumsq;
    __nv_bfloat16 *p_w1h, *p_w1l, *p_w2h, *p_w2l, *p_xh, *p_xl;
    cudaGetSymbolAddress((void**)&p_h, g_h);
    cudaGetSymbolAddress((void**)&p_z, g_z);
    cudaGetSymbolAddress((void**)&p_sum, g_sum);
    cudaGetSymbolAddress((void**)&p_sumsq, g_sumsq);
    cudaGetSymbolAddress((void**)&p_hsum, g_hsum);
    cudaGetSymbolAddress((void**)&p_hsumsq, g_hsumsq);
    cudaGetSymbolAddress((void**)&p_w1h, g_w1h);
    cudaGetSymbolAddress((void**)&p_w1l, g_w1l);
    cudaGetSymbolAddress((void**)&p_w2h, g_w2h);
    cudaGetSymbolAddress((void**)&p_w2l, g_w2l);
    cudaGetSymbolAddress((void**)&p_xh, g_xh);
    cudaGetSymbolAddress((void**)&p_xl, g_xl);

    // ---- CSR build + encoders + weight prep ----
    k_zero_deg<<<(NN + 255) / 256, 256>>>();
    k_hist<<<(EE + 255) / 256, 256>>>(dst);
    k_scan1<<<NSB, 1024>>>();
    k_scan2<<<1, 32>>>();
    k_scan3<<<(NN + 255) / 256, 256>>>();
    k_scatter<<<(EE + 255) / 256, 256>>>(src, dst, eattr);
    k_atom<<<(NN * DD + 255) / 256, 256>>>(x, aoff, atab);
    k_btab<<<(NCOMBO * DD + 255) / 256, 256>>>(boff, btab);
    k_wprep1<<<(LL * D2 * DD + 255) / 256, 256>>>(w1);
    k_wprep2<<<(LL * DD * D2 + 255) / 256, 256>>>(w2);
    k_zero_stats<<<1, 256>>>();

    for (int l = 0; l < LL; l++) {
        if (l > 0)
            k_bnfin_h<<<1, 256>>>(ngamma + l * DD, nbeta + l * DD);   // also zeros z-stats
        k_prenorm<<<(NN * DD / 2 + 255) / 256, 256>>>(l > 0 ? 1 : 0);
        k_aggr<<<NN, 128>>>(tarr, l, l > 0 ? 1 : 0);
        k_gemm1<<<dim3(MT, 2), 512>>>(
            p_xh, p_xl, p_w1h + (size_t)l * D2 * DD, p_w1l + (size_t)l * D2 * DD,
            b1 + l * D2, p_z, p_sum, p_sumsq);
        k_bnfin_z<<<1, 256>>>(bng + l * D2, bnb + l * D2);            // also zeros h-stats
        if (l == 0)
            k_gemm2<false><<<MT, 512>>>(
                p_z, p_w2h + (size_t)l * DD * D2, p_w2l + (size_t)l * DD * D2,
                b2 + l * DD, p_h, p_hsum, p_hsumsq);
        else
            k_gemm2<true><<<MT, 512>>>(
                p_z, p_w2h + (size_t)l * DD * D2, p_w2l + (size_t)l * DD * D2,
                b2 + l * DD, p_h, p_hsum, p_hsumsq);
    }

    // ---- final norm + pool + predict ----
    k_bnfin_h<<<1, 256>>>(ngamma, nbeta);
    k_zero_pool<<<(BB * DD + 255) / 256, 256>>>();
    k_pool<<<(NN * DD + 255) / 256, 256>>>(batch);
    k_pred<<<BB, 128>>>(pw, pb, out);
}